// round 12
// baseline (speedup 1.0000x reference)
#include <cuda_runtime.h>
#include <cuda_bf16.h>

// Problem constants: B=16, V=4096, E=768
#define BB 16
#define VV 4096
#define EE 768
#define GRID_P 888   // 148 SMs x 6 resident CTAs (natural ~54 regs, 192 thr)

// out[b,v,e] = seq[b,v,0]*flux_w[v,e] + flux_b[v,e]
//            + seq[b,v,2]*time_w[v,e] + time_b[v,e]
//            + (e even ? sin : cos)( seq[b,v,1] * exp(-e_even*ln(10000)/E) )
//
// R11: persistent grid. Evidence from R3-R10: kernel is at the ~5.2 TB/s
// write-only HBM ceiling (5 distinct store paths converge there; occupancy
// 47%-82% makes no difference; traffic is compulsory 201 MB of writes).
// The only remaining slack is wave quantization (4096 CTAs / 888 concurrent
// = 4.61 waves: ragged tail + ~4 wave transitions). Launch exactly 888 CTAs,
// each looping v += 888 over 4-5 vocab rows -> zero wave transitions, no
// tail, and next-v weight loads overlap prior-v store drain.
// Body = proven R3 body: plain LDG.128 / STG.128, register-resident weights,
// __sincosf, no smem, no syncs.
__global__ __launch_bounds__(192) void bert_embed_kernel(
    const float* __restrict__ seq,   // [B, V, 3]
    const float* __restrict__ fw,    // [V, E]
    const float* __restrict__ fb,    // [V, E]
    const float* __restrict__ tw,    // [V, E]
    const float* __restrict__ tb,    // [V, E]
    float* __restrict__ out)         // [B, V, E]
{
    const int t = threadIdx.x;
    const int e = t * 4;                       // even-aligned

    // div_term depends only on e — hoisted out of the persistent loop.
    // div_term[i] = exp(2i * (-ln(10000)/E)); here 2i = e and e+2.
    const float c  = -9.210340371976184f / (float)EE;   // -ln(10000)/E
    const float d0 = __expf((float)e * c);
    const float d1 = __expf((float)(e + 2) * c);

    for (int v = blockIdx.x; v < VV; v += GRID_P) {
        const size_t base = (size_t)v * EE + e;

        // Compulsory weight reads, register-resident across the batch loop.
        const float4 wf = *reinterpret_cast<const float4*>(fw + base);
        const float4 bf = *reinterpret_cast<const float4*>(fb + base);
        const float4 wt = *reinterpret_cast<const float4*>(tw + base);
        const float4 bt = *reinterpret_cast<const float4*>(tb + base);
        const float4 bs = make_float4(bf.x + bt.x, bf.y + bt.y,
                                      bf.z + bt.z, bf.w + bt.w);

        #pragma unroll
        for (int b = 0; b < BB; b++) {
            const float* s = seq + ((size_t)b * VV + v) * 3;
            const float s0 = __ldg(s + 0);   // flux (L2-broadcast)
            const float s1 = __ldg(s + 1);   // passend
            const float s2 = __ldg(s + 2);   // time

            float sin0, cos0, sin1, cos1;
            __sincosf(s1 * d0, &sin0, &cos0);
            __sincosf(s1 * d1, &sin1, &cos1);

            float4 o;
            o.x = fmaf(s0, wf.x, fmaf(s2, wt.x, bs.x)) + sin0;
            o.y = fmaf(s0, wf.y, fmaf(s2, wt.y, bs.y)) + cos0;
            o.z = fmaf(s0, wf.z, fmaf(s2, wt.z, bs.z)) + sin1;
            o.w = fmaf(s0, wf.w, fmaf(s2, wt.w, bs.w)) + cos1;

            // Plain cached store (STG.128) — best-measured write path.
            *reinterpret_cast<float4*>(out + (size_t)b * (VV * EE) + base) = o;
        }
    }
}

extern "C" void kernel_launch(void* const* d_in, const int* in_sizes, int n_in,
                              void* d_out, int out_size)
{
    const float* seq = (const float*)d_in[0];  // sequence [B,V,3]
    const float* fw  = (const float*)d_in[1];  // flux_w   [V,E]
    const float* fb  = (const float*)d_in[2];  // flux_b   [V,E]
    const float* tw  = (const float*)d_in[3];  // time_w   [V,E]
    const float* tb  = (const float*)d_in[4];  // time_b   [V,E]
    float* out = (float*)d_out;                // [B,V,E]

    dim3 grid(GRID_P);
    dim3 block(EE / 4);  // 192 threads
    bert_embed_kernel<<<grid, block>>>(seq, fw, fb, tw, tb, out);
}

// round 13
// speedup vs baseline: 1.1302x; 1.1302x over previous
#include <cuda_runtime.h>
#include <cuda_bf16.h>

// Problem constants (from reference): B=16, V=4096, E=768
#define BB 16
#define VV 4096
#define EE 768

// out[b,v,e] = seq[b,v,0]*flux_w[v,e] + flux_b[v,e]
//            + seq[b,v,2]*time_w[v,e] + time_b[v,e]
//            + (e even ? sin : cos)( seq[b,v,1] * exp(-e_even*ln(10000)/E) )
//
// FINAL (= R3, measured best 43.07us, 5.24 TB/s DRAM).
// One block per v (4096 blocks), 192 threads, each thread owns 4 consecutive e.
// Weights are loaded ONCE per (v,e) into registers; the b-loop reuses them,
// keeping weight traffic compulsory (L2-resident across graph replays).
// Kernel sits at the empirical write-only HBM ceiling (~5.2 TB/s):
//  - store-path variants (.cs, evict_last, TMA bulk) regress or are neutral
//  - occupancy 47%..82% makes no difference
//  - persistent grid regresses (loses cross-CTA MLP)
// Plain LDG.128 / STG.128 with the hardware scheduler's wave overlap is the
// measured optimum.
__global__ __launch_bounds__(192) void bert_embed_kernel(
    const float* __restrict__ seq,   // [B, V, 3]
    const float* __restrict__ fw,    // [V, E]
    const float* __restrict__ fb,    // [V, E]
    const float* __restrict__ tw,    // [V, E]
    const float* __restrict__ tb,    // [V, E]
    float* __restrict__ out)         // [B, V, E]
{
    const int v = blockIdx.x;
    const int e = threadIdx.x * 4;           // even-aligned
    const size_t base = (size_t)v * EE + e;

    // Compulsory weight reads, kept in registers across the batch loop.
    const float4 wf = *reinterpret_cast<const float4*>(fw + base);
    const float4 bf = *reinterpret_cast<const float4*>(fb + base);
    const float4 wt = *reinterpret_cast<const float4*>(tw + base);
    const float4 bt = *reinterpret_cast<const float4*>(tb + base);

    // div_term for the two sin/cos pairs this thread owns.
    // div_term[i] = exp(2i * (-ln(10000)/E)); here 2i = e and e+2.
    const float c = -9.210340371976184f / (float)EE;   // -ln(10000)/E
    const float d0 = __expf((float)e * c);
    const float d1 = __expf((float)(e + 2) * c);

    #pragma unroll
    for (int b = 0; b < BB; b++) {
        const float* s = seq + ((size_t)b * VV + v) * 3;
        const float s0 = __ldg(s + 0);   // flux scalar (broadcast across block)
        const float s1 = __ldg(s + 1);   // passend
        const float s2 = __ldg(s + 2);   // time

        float sin0, cos0, sin1, cos1;
        __sincosf(s1 * d0, &sin0, &cos0);
        __sincosf(s1 * d1, &sin1, &cos1);

        float4 o;
        o.x = fmaf(s0, wf.x, bf.x) + fmaf(s2, wt.x, bt.x) + sin0;
        o.y = fmaf(s0, wf.y, bf.y) + fmaf(s2, wt.y, bt.y) + cos0;
        o.z = fmaf(s0, wf.z, bf.z) + fmaf(s2, wt.z, bt.z) + sin1;
        o.w = fmaf(s0, wf.w, bf.w) + fmaf(s2, wt.w, bt.w) + cos1;

        *reinterpret_cast<float4*>(out + (size_t)b * (VV * EE) + base) = o;
    }
}

extern "C" void kernel_launch(void* const* d_in, const int* in_sizes, int n_in,
                              void* d_out, int out_size)
{
    const float* seq = (const float*)d_in[0];  // sequence [B,V,3]
    const float* fw  = (const float*)d_in[1];  // flux_w   [V,E]
    const float* fb  = (const float*)d_in[2];  // flux_b   [V,E]
    const float* tw  = (const float*)d_in[3];  // time_w   [V,E]
    const float* tb  = (const float*)d_in[4];  // time_b   [V,E]
    float* out = (float*)d_out;                // [B,V,E]

    dim3 grid(VV);
    dim3 block(EE / 4);  // 192 threads
    bert_embed_kernel<<<grid, block>>>(seq, fw, fb, tw, tb, out);
}